// round 15
// baseline (speedup 1.0000x reference)
#include <cuda_runtime.h>

#define N_NODES 50000
#define N_EDGES 800000
#define D 128
#define TOT_EDGES (2 * N_EDGES)

#define SCAN_BLK 512
#define SCAN_NBLK ((N_NODES + SCAN_BLK - 1) / SCAN_BLK)   // 98

// ---------------------------------------------------------------------------
// Static scratch (no allocations allowed). Zero-initialized at load; the
// zero invariant for g_count/g_ticket/g_total is re-established every call.
// ---------------------------------------------------------------------------
__device__ float g_alpha[N_NODES];
__device__ int   g_count[N_NODES];
__device__ int   g_start[N_NODES];
__device__ int   g_end[N_NODES];
__device__ int   g_cursor[N_NODES];
__device__ int   g_ticket;
__device__ int   g_total;
__device__ __align__(16) int2 g_edges[TOT_EDGES + 64];   // (col, scaled_val)

// ---------------------------------------------------------------------------
// K1: FUSED alpha + histogram. Warp w: alpha_w = sigmoid(x_w . aw + ab).
//     Thread i: histogram edge i's destination row (REDG).
// ---------------------------------------------------------------------------
__global__ void alpha_hist_kernel(const float* __restrict__ x,
                                  const float* __restrict__ aw,
                                  const float* __restrict__ ab,
                                  const int* __restrict__ lp_rows,
                                  const int* __restrict__ hp_rows,
                                  float* __restrict__ alpha_out) {
    int gtid = blockIdx.x * blockDim.x + threadIdx.x;
    if (gtid == 0) { g_ticket = 0; g_total = 0; }

    if (gtid < TOT_EDGES) {
        int r = (gtid < N_EDGES) ? __ldg(lp_rows + gtid)
                                 : __ldg(hp_rows + (gtid - N_EDGES));
        atomicAdd(&g_count[r], 1);   // no return use -> REDG
    }

    int warp = gtid >> 5;
    int lane = threadIdx.x & 31;
    if (warp >= N_NODES) return;
    float4 xv = reinterpret_cast<const float4*>(x)[warp * 32 + lane];
    float4 wv = reinterpret_cast<const float4*>(aw)[lane];
    float s = xv.x * wv.x + xv.y * wv.y + xv.z * wv.z + xv.w * wv.w;
    #pragma unroll
    for (int o = 16; o; o >>= 1) s += __shfl_xor_sync(0xFFFFFFFFu, s, o);
    if (lane == 0) {
        s += ab[0];
        float a = 1.0f / (1.0f + expf(-s));
        g_alpha[warp] = a;
        alpha_out[warp] = a;
    }
}

// ---------------------------------------------------------------------------
// K2: single-pass scan. Block base via atomicAdd(&g_total, block_sum);
//     bucket order across blocks is arbitrary. Emits start/end/cursor and
//     zeroes g_count (fused kernel stays read-only).
// ---------------------------------------------------------------------------
__global__ void __launch_bounds__(SCAN_BLK)
scan_kernel() {
    __shared__ int wsum[SCAN_BLK / 32];
    __shared__ int sbase;
    int t = threadIdx.x;
    int i = blockIdx.x * SCAN_BLK + t;
    int lane = t & 31;
    int wid = t >> 5;

    int v = (i < N_NODES) ? g_count[i] : 0;

    int inc = v;
    #pragma unroll
    for (int o = 1; o < 32; o <<= 1) {
        int n = __shfl_up_sync(0xFFFFFFFFu, inc, o);
        if (lane >= o) inc += n;
    }
    if (lane == 31) wsum[wid] = inc;
    __syncthreads();

    if (wid == 0) {
        int ws = (lane < SCAN_BLK / 32) ? wsum[lane] : 0;
        int wi = ws;
        #pragma unroll
        for (int o = 1; o < SCAN_BLK / 32; o <<= 1) {
            int n = __shfl_up_sync(0xFFFFFFFFu, wi, o);
            if (lane >= o) wi += n;
        }
        if (lane < SCAN_BLK / 32) wsum[lane] = wi - ws;
        if (lane == SCAN_BLK / 32 - 1)
            sbase = atomicAdd(&g_total, wi);
    }
    __syncthreads();

    if (i < N_NODES) {
        int s = sbase + wsum[wid] + inc - v;
        g_start[i]  = s;
        g_end[i]    = s + v;
        g_cursor[i] = s;
        g_count[i]  = 0;
    }
}

// ---------------------------------------------------------------------------
// K3: scatter edges into row-bucketed list, pre-scaled by the gate.
// ---------------------------------------------------------------------------
__global__ void scatter_kernel(const int* __restrict__ lp_rows,
                               const int* __restrict__ lp_cols,
                               const float* __restrict__ lp_vals,
                               const int* __restrict__ hp_rows,
                               const int* __restrict__ hp_cols,
                               const float* __restrict__ hp_vals) {
    int i = blockIdx.x * blockDim.x + threadIdx.x;
    if (i >= TOT_EDGES) return;
    int r, c; float v;
    if (i < N_EDGES) {
        r = __ldg(lp_rows + i);
        c = __ldg(lp_cols + i);
        v = __ldg(lp_vals + i) * g_alpha[r];
    } else {
        int e = i - N_EDGES;
        r = __ldg(hp_rows + e);
        c = __ldg(hp_cols + e);
        v = __ldg(hp_vals + e) * (1.0f - g_alpha[r]);
    }
    int pos = atomicAdd(&g_cursor[r], 1);
    g_edges[pos] = make_int2(c, __float_as_int(v));
}

// ---------------------------------------------------------------------------
// K4: FUSED gather + GEMM + relu, warp-pair 8-row blocked, persistent.
//   A pair of warps (2p, 2p+1) co-processes 8 rows: each warp gathers 4 rows
//   (R14's 4-way unrolled loop), then each warp computes a 64-column half of
//   the output for all 8 rows -> Wt smem traffic halved vs 4-row blocking.
//   Pair sync via named barriers (id = pair+1, 64 threads).
// ---------------------------------------------------------------------------
#define FG_BLOCKS 296   // 2 per SM
__global__ void __launch_bounds__(512, 2)
fused_gather_gemm_kernel(const float* __restrict__ x,
                         const float* __restrict__ W,
                         const float* __restrict__ b,
                         float* __restrict__ out) {
    extern __shared__ float sm[];
    float* Wt = sm;                                   // [128][132] = 67.6KB
    float* zs = sm + 128 * 132;                       // [8 pairs][8][128] = 32KB
    int2*  es = (int2*)(sm + 128 * 132 + 8 * 8 * 128);    // [16][32] = 4KB
    int*   pticket = (int*)(es + 16 * 32);                // [8]

    int tid  = threadIdx.x;
    int warp = tid >> 5;
    int lane = tid & 31;
    int pair = warp >> 1;
    int half = warp & 1;
    int barid = pair + 1;   // named barrier per pair (0 reserved for syncthreads)

    // Stage + transpose W: Wt[k][c] = W[c*128 + k]
    for (int idx = tid; idx < D * D; idx += 512) {
        int c = idx >> 7;
        int k = idx & 127;
        Wt[k * 132 + c] = W[idx];
    }
    __syncthreads();

    float2 bv2 = *reinterpret_cast<const float2*>(b + half * 64 + lane * 2);
    const float4* x4 = reinterpret_cast<const float4*>(x);
    float* zp = zs + pair * 8 * D;     // pair's 8 staged z rows
    int2*  eq = es + warp * 32;        // per-warp edge stage

    const int n_octs = (N_NODES + 7) / 8;   // 6250

    while (true) {
        // Pair-shared ticket. This barrier also guarantees the partner warp
        // finished the previous GEMM before zp is overwritten.
        asm volatile("bar.sync %0, %1;" :: "r"(barid), "r"(64) : "memory");
        if (half == 0 && lane == 0) pticket[pair] = atomicAdd(&g_ticket, 1);
        asm volatile("bar.sync %0, %1;" :: "r"(barid), "r"(64) : "memory");
        int oct = pticket[pair];
        if (oct >= n_octs) break;
        int row0 = oct * 8;

        // ---- gather phase: this warp's 4 rows into the pair tile ----
        #pragma unroll
        for (int rr = 0; rr < 4; rr++) {
            int rloc = half * 4 + rr;
            int row = row0 + rloc;
            float4 acc0 = make_float4(0.f, 0.f, 0.f, 0.f);
            float4 acc1 = make_float4(0.f, 0.f, 0.f, 0.f);
            if (row < N_NODES) {
                int s = __ldg(&g_start[row]);
                int e = __ldg(&g_end[row]);
                for (int base = s; base < e; base += 32) {
                    int rem = e - base;
                    int m = rem < 32 ? rem : 32;
                    __syncwarp();
                    if (lane < m) eq[lane] = __ldg(&g_edges[base + lane]);
                    __syncwarp();

                    int j = 0;
                    for (; j + 3 < m; j += 4) {
                        int2 e0 = eq[j];
                        int2 e1 = eq[j + 1];
                        int2 e2 = eq[j + 2];
                        int2 e3 = eq[j + 3];
                        float4 xv0 = __ldg(x4 + (long long)e0.x * 32 + lane);
                        float4 xv1 = __ldg(x4 + (long long)e1.x * 32 + lane);
                        float4 xv2 = __ldg(x4 + (long long)e2.x * 32 + lane);
                        float4 xv3 = __ldg(x4 + (long long)e3.x * 32 + lane);
                        float v0 = __int_as_float(e0.y);
                        float v1 = __int_as_float(e1.y);
                        float v2 = __int_as_float(e2.y);
                        float v3 = __int_as_float(e3.y);
                        acc0.x += v0 * xv0.x; acc0.y += v0 * xv0.y;
                        acc0.z += v0 * xv0.z; acc0.w += v0 * xv0.w;
                        acc1.x += v1 * xv1.x; acc1.y += v1 * xv1.y;
                        acc1.z += v1 * xv1.z; acc1.w += v1 * xv1.w;
                        acc0.x += v2 * xv2.x; acc0.y += v2 * xv2.y;
                        acc0.z += v2 * xv2.z; acc0.w += v2 * xv2.w;
                        acc1.x += v3 * xv3.x; acc1.y += v3 * xv3.y;
                        acc1.z += v3 * xv3.z; acc1.w += v3 * xv3.w;
                    }
                    for (; j < m; j++) {
                        int2 e0 = eq[j];
                        float v0 = __int_as_float(e0.y);
                        float4 xv0 = __ldg(x4 + (long long)e0.x * 32 + lane);
                        acc0.x += v0 * xv0.x; acc0.y += v0 * xv0.y;
                        acc0.z += v0 * xv0.z; acc0.w += v0 * xv0.w;
                    }
                }
            }
            float4 z;
            z.x = acc0.x + acc1.x; z.y = acc0.y + acc1.y;
            z.z = acc0.z + acc1.z; z.w = acc0.w + acc1.w;
            reinterpret_cast<float4*>(zp + rloc * D)[lane] = z;
        }

        // Pair barrier: all 8 z rows staged (bar.sync drains STS).
        asm volatile("bar.sync %0, %1;" :: "r"(barid), "r"(64) : "memory");

        // ---- GEMM phase: 8 rows x this warp's 64-col half ----
        float acc[8][2];
        #pragma unroll
        for (int i = 0; i < 8; i++) { acc[i][0] = 0.f; acc[i][1] = 0.f; }

        const float* wcol = Wt + half * 64 + lane * 2;

        #pragma unroll 4
        for (int k0 = 0; k0 < D; k0 += 4) {
            float2 w0 = *reinterpret_cast<const float2*>(wcol + (k0 + 0) * 132);
            float2 w1 = *reinterpret_cast<const float2*>(wcol + (k0 + 1) * 132);
            float2 w2 = *reinterpret_cast<const float2*>(wcol + (k0 + 2) * 132);
            float2 w3 = *reinterpret_cast<const float2*>(wcol + (k0 + 3) * 132);

            #pragma unroll
            for (int rr = 0; rr < 8; rr++) {
                float4 z4 = *reinterpret_cast<const float4*>(zp + rr * D + k0);  // broadcast
                acc[rr][0] += z4.x * w0.x + z4.y * w1.x + z4.z * w2.x + z4.w * w3.x;
                acc[rr][1] += z4.x * w0.y + z4.y * w1.y + z4.z * w2.y + z4.w * w3.y;
            }
        }

        #pragma unroll
        for (int rr = 0; rr < 8; rr++) {
            int row = row0 + rr;
            if (row < N_NODES) {
                float2 o;
                o.x = fmaxf(acc[rr][0] + bv2.x, 0.f);
                o.y = fmaxf(acc[rr][1] + bv2.y, 0.f);
                *reinterpret_cast<float2*>(out + (long long)row * D + half * 64 + lane * 2) = o;
            }
        }
    }
}

// ---------------------------------------------------------------------------
extern "C" void kernel_launch(void* const* d_in, const int* in_sizes, int n_in,
                              void* d_out, int out_size) {
    const float* x   = (const float*)d_in[0];
    const int*   lpr = (const int*)  d_in[1];
    const int*   lpc = (const int*)  d_in[2];
    const float* lpv = (const float*)d_in[3];
    const int*   hpr = (const int*)  d_in[4];
    const int*   hpc = (const int*)  d_in[5];
    const float* hpv = (const float*)d_in[6];
    const float* aw  = (const float*)d_in[7];
    const float* ab  = (const float*)d_in[8];
    const float* W   = (const float*)d_in[9];
    const float* b   = (const float*)d_in[10];

    float* out       = (float*)d_out;
    float* alpha_out = out + (long long)N_NODES * D;

    const int fg_smem = (128 * 132 + 8 * 8 * 128) * sizeof(float)
                        + 16 * 32 * sizeof(int2) + 8 * sizeof(int);  // 104480
    cudaFuncSetAttribute(fused_gather_gemm_kernel,
                         cudaFuncAttributeMaxDynamicSharedMemorySize, fg_smem);

    alpha_hist_kernel<<<TOT_EDGES / 256, 256>>>(x, aw, ab, lpr, hpr, alpha_out);
    scan_kernel<<<SCAN_NBLK, SCAN_BLK>>>();
    scatter_kernel<<<(TOT_EDGES + 255) / 256, 256>>>(lpr, lpc, lpv, hpr, hpc, hpv);
    fused_gather_gemm_kernel<<<FG_BLOCKS, 512, fg_smem>>>(x, W, b, out);
}

// round 16
// speedup vs baseline: 1.0927x; 1.0927x over previous
#include <cuda_runtime.h>
#include <cuda_fp16.h>

#define N_NODES 50000
#define N_EDGES 800000
#define D 128
#define TOT_EDGES (2 * N_EDGES)

#define SCAN_BLK 512
#define SCAN_NBLK ((N_NODES + SCAN_BLK - 1) / SCAN_BLK)   // 98

// ---------------------------------------------------------------------------
// Static scratch (no allocations allowed). Zero-initialized at load; the
// zero invariant for g_count/g_ticket/g_total is re-established every call.
// ---------------------------------------------------------------------------
__device__ float g_alpha[N_NODES];
__device__ int   g_count[N_NODES];
__device__ int   g_start[N_NODES];
__device__ int   g_end[N_NODES];
__device__ int   g_cursor[N_NODES];
__device__ int   g_ticket;
__device__ int   g_total;
__device__ __align__(16) int2   g_edges[TOT_EDGES + 64];  // (col, scaled_val)
__device__ __align__(16) __half g_xh[N_NODES * D];        // fp16 copy of x

// ---------------------------------------------------------------------------
// K1: FUSED alpha + histogram + fp16 x conversion.
//   Warp w: alpha_w = sigmoid(x_w . aw + ab); each lane also writes its 4
//   channels of x as fp16 (the gather operand).
//   Thread i: histogram edge i's destination row (REDG).
// ---------------------------------------------------------------------------
__global__ void alpha_hist_kernel(const float* __restrict__ x,
                                  const float* __restrict__ aw,
                                  const float* __restrict__ ab,
                                  const int* __restrict__ lp_rows,
                                  const int* __restrict__ hp_rows,
                                  float* __restrict__ alpha_out) {
    int gtid = blockIdx.x * blockDim.x + threadIdx.x;
    if (gtid == 0) { g_ticket = 0; g_total = 0; }

    if (gtid < TOT_EDGES) {
        int r = (gtid < N_EDGES) ? __ldg(lp_rows + gtid)
                                 : __ldg(hp_rows + (gtid - N_EDGES));
        atomicAdd(&g_count[r], 1);   // no return use -> REDG
    }

    int warp = gtid >> 5;
    int lane = threadIdx.x & 31;
    if (warp >= N_NODES) return;
    float4 xv = reinterpret_cast<const float4*>(x)[warp * 32 + lane];

    // fp16 conversion of this lane's 4 channels
    __half2 h01 = __floats2half2_rn(xv.x, xv.y);
    __half2 h23 = __floats2half2_rn(xv.z, xv.w);
    uint2 packed;
    packed.x = *reinterpret_cast<unsigned*>(&h01);
    packed.y = *reinterpret_cast<unsigned*>(&h23);
    reinterpret_cast<uint2*>(g_xh)[warp * 32 + lane] = packed;

    float4 wv = reinterpret_cast<const float4*>(aw)[lane];
    float s = xv.x * wv.x + xv.y * wv.y + xv.z * wv.z + xv.w * wv.w;
    #pragma unroll
    for (int o = 16; o; o >>= 1) s += __shfl_xor_sync(0xFFFFFFFFu, s, o);
    if (lane == 0) {
        s += ab[0];
        float a = 1.0f / (1.0f + expf(-s));
        g_alpha[warp] = a;
        alpha_out[warp] = a;
    }
}

// ---------------------------------------------------------------------------
// K2: single-pass scan. Block base via atomicAdd(&g_total, block_sum);
//     bucket order across blocks is arbitrary. Emits start/end/cursor and
//     zeroes g_count (fused kernel stays read-only).
// ---------------------------------------------------------------------------
__global__ void __launch_bounds__(SCAN_BLK)
scan_kernel() {
    __shared__ int wsum[SCAN_BLK / 32];
    __shared__ int sbase;
    int t = threadIdx.x;
    int i = blockIdx.x * SCAN_BLK + t;
    int lane = t & 31;
    int wid = t >> 5;

    int v = (i < N_NODES) ? g_count[i] : 0;

    int inc = v;
    #pragma unroll
    for (int o = 1; o < 32; o <<= 1) {
        int n = __shfl_up_sync(0xFFFFFFFFu, inc, o);
        if (lane >= o) inc += n;
    }
    if (lane == 31) wsum[wid] = inc;
    __syncthreads();

    if (wid == 0) {
        int ws = (lane < SCAN_BLK / 32) ? wsum[lane] : 0;
        int wi = ws;
        #pragma unroll
        for (int o = 1; o < SCAN_BLK / 32; o <<= 1) {
            int n = __shfl_up_sync(0xFFFFFFFFu, wi, o);
            if (lane >= o) wi += n;
        }
        if (lane < SCAN_BLK / 32) wsum[lane] = wi - ws;
        if (lane == SCAN_BLK / 32 - 1)
            sbase = atomicAdd(&g_total, wi);
    }
    __syncthreads();

    if (i < N_NODES) {
        int s = sbase + wsum[wid] + inc - v;
        g_start[i]  = s;
        g_end[i]    = s + v;
        g_cursor[i] = s;
        g_count[i]  = 0;
    }
}

// ---------------------------------------------------------------------------
// K3: scatter edges into row-bucketed list, pre-scaled by the gate.
// ---------------------------------------------------------------------------
__global__ void scatter_kernel(const int* __restrict__ lp_rows,
                               const int* __restrict__ lp_cols,
                               const float* __restrict__ lp_vals,
                               const int* __restrict__ hp_rows,
                               const int* __restrict__ hp_cols,
                               const float* __restrict__ hp_vals) {
    int i = blockIdx.x * blockDim.x + threadIdx.x;
    if (i >= TOT_EDGES) return;
    int r, c; float v;
    if (i < N_EDGES) {
        r = __ldg(lp_rows + i);
        c = __ldg(lp_cols + i);
        v = __ldg(lp_vals + i) * g_alpha[r];
    } else {
        int e = i - N_EDGES;
        r = __ldg(hp_rows + e);
        c = __ldg(hp_cols + e);
        v = __ldg(hp_vals + e) * (1.0f - g_alpha[r]);
    }
    int pos = atomicAdd(&g_cursor[r], 1);
    g_edges[pos] = make_int2(c, __float_as_int(v));
}

// ---------------------------------------------------------------------------
// K4: FUSED gather + GEMM + relu, 4-row blocked, persistent (R14 structure).
//   Gather reads the fp16 x copy (256B/edge -> 2 L1 wavefronts instead of 4).
//   4-way unrolled main body (4 independent LDG.64 in flight) + scalar tail.
//   Accumulation and GEMM remain fully fp32.
// ---------------------------------------------------------------------------
#define FG_BLOCKS 296   // 2 per SM
__global__ void __launch_bounds__(512, 2)
fused_gather_gemm_kernel(const float* __restrict__ W,
                         const float* __restrict__ b,
                         float* __restrict__ out) {
    extern __shared__ float sm[];
    float* Wt = sm;                                  // [128][132] = 67.6KB
    float* zs = sm + 128 * 132;                      // [16][4][128] = 32KB
    int2*  es = (int2*)(sm + 128 * 132 + 16 * 4 * 128);  // [16][32] = 4KB

    int tid  = threadIdx.x;
    int warp = tid >> 5;
    int lane = tid & 31;

    // Stage + transpose W: Wt[k][c] = W[c*128 + k]
    for (int idx = tid; idx < D * D; idx += 512) {
        int c = idx >> 7;
        int k = idx & 127;
        Wt[k * 132 + c] = W[idx];
    }
    __syncthreads();

    float4 bv = reinterpret_cast<const float4*>(b)[lane];
    const uint2* xh2 = reinterpret_cast<const uint2*>(g_xh);  // 4 halves per uint2
    float* zq = zs + warp * 4 * D;     // this warp's 4 staged rows
    int2*  eq = es + warp * 32;        // this warp's edge stage

    const int n_quads = (N_NODES + 3) / 4;   // 12500

    while (true) {
        int quad;
        if (lane == 0) quad = atomicAdd(&g_ticket, 1);
        quad = __shfl_sync(0xFFFFFFFFu, quad, 0);
        if (quad >= n_quads) break;
        int row0 = quad * 4;

        // ---- gather phase: 4 rows into smem ----
        #pragma unroll
        for (int rr = 0; rr < 4; rr++) {
            int row = row0 + rr;
            float4 acc0 = make_float4(0.f, 0.f, 0.f, 0.f);
            float4 acc1 = make_float4(0.f, 0.f, 0.f, 0.f);
            if (row < N_NODES) {
                int s = __ldg(&g_start[row]);
                int e = __ldg(&g_end[row]);
                for (int base = s; base < e; base += 32) {
                    int rem = e - base;
                    int m = rem < 32 ? rem : 32;
                    __syncwarp();
                    if (lane < m) eq[lane] = __ldg(&g_edges[base + lane]);
                    __syncwarp();

                    int j = 0;
                    // main body: 4 independent LDG.64 gathers in flight
                    for (; j + 3 < m; j += 4) {
                        int2 e0 = eq[j];
                        int2 e1 = eq[j + 1];
                        int2 e2 = eq[j + 2];
                        int2 e3 = eq[j + 3];
                        uint2 p0 = __ldg(xh2 + (long long)e0.x * 32 + lane);
                        uint2 p1 = __ldg(xh2 + (long long)e1.x * 32 + lane);
                        uint2 p2 = __ldg(xh2 + (long long)e2.x * 32 + lane);
                        uint2 p3 = __ldg(xh2 + (long long)e3.x * 32 + lane);
                        float v0 = __int_as_float(e0.y);
                        float v1 = __int_as_float(e1.y);
                        float v2 = __int_as_float(e2.y);
                        float v3 = __int_as_float(e3.y);

                        float2 a01 = __half22float2(*reinterpret_cast<__half2*>(&p0.x));
                        float2 a23 = __half22float2(*reinterpret_cast<__half2*>(&p0.y));
                        acc0.x += v0 * a01.x; acc0.y += v0 * a01.y;
                        acc0.z += v0 * a23.x; acc0.w += v0 * a23.y;

                        float2 b01 = __half22float2(*reinterpret_cast<__half2*>(&p1.x));
                        float2 b23 = __half22float2(*reinterpret_cast<__half2*>(&p1.y));
                        acc1.x += v1 * b01.x; acc1.y += v1 * b01.y;
                        acc1.z += v1 * b23.x; acc1.w += v1 * b23.y;

                        float2 c01 = __half22float2(*reinterpret_cast<__half2*>(&p2.x));
                        float2 c23 = __half22float2(*reinterpret_cast<__half2*>(&p2.y));
                        acc0.x += v2 * c01.x; acc0.y += v2 * c01.y;
                        acc0.z += v2 * c23.x; acc0.w += v2 * c23.y;

                        float2 d01 = __half22float2(*reinterpret_cast<__half2*>(&p3.x));
                        float2 d23 = __half22float2(*reinterpret_cast<__half2*>(&p3.y));
                        acc1.x += v3 * d01.x; acc1.y += v3 * d01.y;
                        acc1.z += v3 * d23.x; acc1.w += v3 * d23.y;
                    }
                    // tail (<= 3 edges)
                    for (; j < m; j++) {
                        int2 e0 = eq[j];
                        float v0 = __int_as_float(e0.y);
                        uint2 p0 = __ldg(xh2 + (long long)e0.x * 32 + lane);
                        float2 a01 = __half22float2(*reinterpret_cast<__half2*>(&p0.x));
                        float2 a23 = __half22float2(*reinterpret_cast<__half2*>(&p0.y));
                        acc0.x += v0 * a01.x; acc0.y += v0 * a01.y;
                        acc0.z += v0 * a23.x; acc0.w += v0 * a23.y;
                    }
                }
            }
            float4 z;
            z.x = acc0.x + acc1.x; z.y = acc0.y + acc1.y;
            z.z = acc0.z + acc1.z; z.w = acc0.w + acc1.w;
            reinterpret_cast<float4*>(zq + rr * D)[lane] = z;
        }
        __syncwarp();

        // ---- GEMM phase: acc[4][4], each Wt load reused across 4 rows ----
        float acc[4][4];
        #pragma unroll
        for (int i = 0; i < 4; i++)
            #pragma unroll
            for (int j = 0; j < 4; j++) acc[i][j] = 0.f;

        #pragma unroll 4
        for (int k0 = 0; k0 < D; k0 += 4) {
            float4 w0 = reinterpret_cast<const float4*>(Wt + (k0 + 0) * 132)[lane];
            float4 w1 = reinterpret_cast<const float4*>(Wt + (k0 + 1) * 132)[lane];
            float4 w2 = reinterpret_cast<const float4*>(Wt + (k0 + 2) * 132)[lane];
            float4 w3 = reinterpret_cast<const float4*>(Wt + (k0 + 3) * 132)[lane];

            #pragma unroll
            for (int rr = 0; rr < 4; rr++) {
                float4 z4 = *reinterpret_cast<const float4*>(zq + rr * D + k0);  // broadcast
                acc[rr][0] += z4.x * w0.x + z4.y * w1.x + z4.z * w2.x + z4.w * w3.x;
                acc[rr][1] += z4.x * w0.y + z4.y * w1.y + z4.z * w2.y + z4.w * w3.y;
                acc[rr][2] += z4.x * w0.z + z4.y * w1.z + z4.z * w2.z + z4.w * w3.z;
                acc[rr][3] += z4.x * w0.w + z4.y * w1.w + z4.z * w2.w + z4.w * w3.w;
            }
        }

        #pragma unroll
        for (int rr = 0; rr < 4; rr++) {
            int row = row0 + rr;
            if (row < N_NODES) {
                float4 o;
                o.x = fmaxf(acc[rr][0] + bv.x, 0.f);
                o.y = fmaxf(acc[rr][1] + bv.y, 0.f);
                o.z = fmaxf(acc[rr][2] + bv.z, 0.f);
                o.w = fmaxf(acc[rr][3] + bv.w, 0.f);
                reinterpret_cast<float4*>(out + (long long)row * D)[lane] = o;
            }
        }
        __syncwarp();
    }
}

// ---------------------------------------------------------------------------
extern "C" void kernel_launch(void* const* d_in, const int* in_sizes, int n_in,
                              void* d_out, int out_size) {
    const float* x   = (const float*)d_in[0];
    const int*   lpr = (const int*)  d_in[1];
    const int*   lpc = (const int*)  d_in[2];
    const float* lpv = (const float*)d_in[3];
    const int*   hpr = (const int*)  d_in[4];
    const int*   hpc = (const int*)  d_in[5];
    const float* hpv = (const float*)d_in[6];
    const float* aw  = (const float*)d_in[7];
    const float* ab  = (const float*)d_in[8];
    const float* W   = (const float*)d_in[9];
    const float* b   = (const float*)d_in[10];

    float* out       = (float*)d_out;
    float* alpha_out = out + (long long)N_NODES * D;

    const int fg_smem = (128 * 132 + 16 * 4 * 128) * sizeof(float)
                        + 16 * 32 * sizeof(int2);   // 104448
    cudaFuncSetAttribute(fused_gather_gemm_kernel,
                         cudaFuncAttributeMaxDynamicSharedMemorySize, fg_smem);

    alpha_hist_kernel<<<TOT_EDGES / 256, 256>>>(x, aw, ab, lpr, hpr, alpha_out);
    scan_kernel<<<SCAN_NBLK, SCAN_BLK>>>();
    scatter_kernel<<<(TOT_EDGES + 255) / 256, 256>>>(lpr, lpc, lpv, hpr, hpc, hpv);
    fused_gather_gemm_kernel<<<FG_BLOCKS, 512, fg_smem>>>(W, b, out);
}